// round 1
// baseline (speedup 1.0000x reference)
#include <cuda_runtime.h>
#include <float.h>

// Problem constants (from reference)
#define B_      8
#define L_      2048
#define D_      256
#define T_      32
#define S_PARA  8
#define S_ADU   24
#define S_SHELL 24

#define D4      (D_ / 4)          // 64 float4 lanes per row
#define ROWS_TOPIC  (B_)                  // 8
#define ROWS_PARA   (B_ * S_PARA)         // 64
#define ROWS_SHELL  (B_ * S_SHELL)        // 192
#define ROWS_ADU    (B_ * S_ADU)          // 192
#define ROWS_TOTAL  (ROWS_TOPIC + ROWS_PARA + ROWS_SHELL + ROWS_ADU)  // 456

// flat output offsets (in float elements), reference return order:
// (topic_out, para_reps, span_reps<-shell, adu_reps<-x)
#define OFF_TOPIC 0
#define OFF_PARA  (B_ * D_)                              // 2048
#define OFF_SHELL (OFF_PARA + B_ * S_PARA * D_)          // 18432
#define OFF_ADU   (OFF_SHELL + B_ * S_SHELL * D_)        // 67584

__device__ __forceinline__ float4 f4max(float4 a, float4 b) {
    float4 r;
    r.x = fmaxf(a.x, b.x);
    r.y = fmaxf(a.y, b.y);
    r.z = fmaxf(a.z, b.z);
    r.w = fmaxf(a.w, b.w);
    return r;
}

__global__ __launch_bounds__(256) void span_maxpool_kernel(
    const float* __restrict__ topic_reps,   // [B,T,D]
    const float* __restrict__ word_reps,    // [B,L,D]
    const int*   __restrict__ para_spans,   // [B,S_PARA,3]
    const int*   __restrict__ x_spans,      // [B,S_ADU,3]
    const int*   __restrict__ shell_spans,  // [B,S_SHELL,3]
    float*       __restrict__ out)
{
    const int row = blockIdx.x * 4 + threadIdx.y;   // 0..455
    const int lane = threadIdx.x;                   // 0..63 (float4 lane)
    if (row >= ROWS_TOTAL) return;

    const float4* src;      // base of first row to pool (at this lane)
    int cnt;                // number of rows to pool (>=1)
    int out_off;            // flat float offset of output row

    if (row < ROWS_TOPIC) {
        // topic: max over T rows of topic_reps[row]
        src = (const float4*)(topic_reps + (size_t)row * T_ * D_) + lane;
        cnt = T_;
        out_off = OFF_TOPIC + row * D_;
    } else if (row < ROWS_TOPIC + ROWS_PARA) {
        const int i = row - ROWS_TOPIC;
        const int* sp = para_spans + i * 3;
        const int elmo = sp[0], start = sp[1], end = sp[2];
        src = (const float4*)(word_reps + ((size_t)elmo * L_ + start) * D_) + lane;
        cnt = end - start + 1;
        out_off = OFF_PARA + i * D_;
    } else if (row < ROWS_TOPIC + ROWS_PARA + ROWS_SHELL) {
        const int i = row - (ROWS_TOPIC + ROWS_PARA);
        const int* sp = shell_spans + i * 3;
        const int elmo = sp[0], start = sp[1], end = sp[2];
        src = (const float4*)(word_reps + ((size_t)elmo * L_ + start) * D_) + lane;
        cnt = end - start + 1;
        out_off = OFF_SHELL + i * D_;
    } else {
        const int i = row - (ROWS_TOPIC + ROWS_PARA + ROWS_SHELL);
        const int* sp = x_spans + i * 3;
        const int elmo = sp[0], start = sp[1], end = sp[2];
        src = (const float4*)(word_reps + ((size_t)elmo * L_ + start) * D_) + lane;
        cnt = end - start + 1;
        out_off = OFF_ADU + i * D_;
    }

    float4 acc = make_float4(-FLT_MAX, -FLT_MAX, -FLT_MAX, -FLT_MAX);

    // 4x unrolled main loop for memory-level parallelism
    int i = 0;
    for (; i + 4 <= cnt; i += 4) {
        float4 v0 = __ldg(src + (size_t)(i + 0) * D4);
        float4 v1 = __ldg(src + (size_t)(i + 1) * D4);
        float4 v2 = __ldg(src + (size_t)(i + 2) * D4);
        float4 v3 = __ldg(src + (size_t)(i + 3) * D4);
        acc = f4max(acc, f4max(f4max(v0, v1), f4max(v2, v3)));
    }
    for (; i < cnt; i++) {
        acc = f4max(acc, __ldg(src + (size_t)i * D4));
    }

    ((float4*)(out + out_off))[lane] = acc;
}

extern "C" void kernel_launch(void* const* d_in, const int* in_sizes, int n_in,
                              void* d_out, int out_size) {
    // metadata order: topic_reps, word_reps, topic_lens(int64, unused),
    //                 para_spans, x_spans, shell_spans
    const float* topic_reps  = (const float*)d_in[0];
    const float* word_reps   = (const float*)d_in[1];
    const int*   para_spans  = (const int*)d_in[3];
    const int*   x_spans     = (const int*)d_in[4];
    const int*   shell_spans = (const int*)d_in[5];
    float* out = (float*)d_out;

    dim3 block(64, 4);
    dim3 grid((ROWS_TOTAL + 3) / 4);   // 114 blocks
    span_maxpool_kernel<<<grid, block>>>(topic_reps, word_reps,
                                         para_spans, x_spans, shell_spans, out);
}

// round 2
// speedup vs baseline: 1.9446x; 1.9446x over previous
#include <cuda_runtime.h>
#include <float.h>

// Problem constants (from reference)
#define B_      8
#define L_      2048
#define D_      256
#define T_      32
#define S_PARA  8
#define S_ADU   24
#define S_SHELL 24

#define D4      (D_ / 4)          // 64 float4 lanes per row
#define ROWS_TOPIC  (B_)                  // 8
#define ROWS_PARA   (B_ * S_PARA)         // 64
#define ROWS_SHELL  (B_ * S_SHELL)        // 192
#define ROWS_ADU    (B_ * S_ADU)          // 192
#define ROWS_TOTAL  (ROWS_TOPIC + ROWS_PARA + ROWS_SHELL + ROWS_ADU)  // 456

// flat output offsets (float elements), reference return order:
// (topic_out, para_reps, span_reps<-shell, adu_reps<-x)
#define OFF_TOPIC 0
#define OFF_PARA  (B_ * D_)                              // 2048
#define OFF_SHELL (OFF_PARA + B_ * S_PARA * D_)          // 18432
#define OFF_ADU   (OFF_SHELL + B_ * S_SHELL * D_)        // 67584

#define YS 4   // span-dimension split per block

__device__ __forceinline__ float4 f4max(float4 a, float4 b) {
    float4 r;
    r.x = fmaxf(a.x, b.x);
    r.y = fmaxf(a.y, b.y);
    r.z = fmaxf(a.z, b.z);
    r.w = fmaxf(a.w, b.w);
    return r;
}

__global__ __launch_bounds__(64 * YS) void span_maxpool_kernel(
    const float* __restrict__ topic_reps,   // [B,T,D]
    const float* __restrict__ word_reps,    // [B,L,D]
    const int*   __restrict__ para_spans,   // [B,S_PARA,3]
    const int*   __restrict__ x_spans,      // [B,S_ADU,3]
    const int*   __restrict__ shell_spans,  // [B,S_SHELL,3]
    float*       __restrict__ out)
{
    __shared__ float4 red[YS][D4];          // 4 KB

    const int row  = blockIdx.x;            // 0..455 (one output row per block)
    const int lane = threadIdx.x;           // 0..63 (float4 lane across D)
    const int ys   = threadIdx.y;           // 0..3  (span-dim slice)

    const float4* src;   // base of first pooled row, at this lane
    int cnt;             // rows to pool (>=1)
    int out_off;         // flat float offset of output row

    if (row < ROWS_TOPIC) {
        src = (const float4*)(topic_reps + (size_t)row * T_ * D_) + lane;
        cnt = T_;
        out_off = OFF_TOPIC + row * D_;
    } else if (row < ROWS_TOPIC + ROWS_PARA) {
        const int i = row - ROWS_TOPIC;
        const int* sp = para_spans + i * 3;
        src = (const float4*)(word_reps + ((size_t)sp[0] * L_ + sp[1]) * D_) + lane;
        cnt = sp[2] - sp[1] + 1;
        out_off = OFF_PARA + i * D_;
    } else if (row < ROWS_TOPIC + ROWS_PARA + ROWS_SHELL) {
        const int i = row - (ROWS_TOPIC + ROWS_PARA);
        const int* sp = shell_spans + i * 3;
        src = (const float4*)(word_reps + ((size_t)sp[0] * L_ + sp[1]) * D_) + lane;
        cnt = sp[2] - sp[1] + 1;
        out_off = OFF_SHELL + i * D_;
    } else {
        const int i = row - (ROWS_TOPIC + ROWS_PARA + ROWS_SHELL);
        const int* sp = x_spans + i * 3;
        src = (const float4*)(word_reps + ((size_t)sp[0] * L_ + sp[1]) * D_) + lane;
        cnt = sp[2] - sp[1] + 1;
        out_off = OFF_ADU + i * D_;
    }

    float4 acc = make_float4(-FLT_MAX, -FLT_MAX, -FLT_MAX, -FLT_MAX);

    // Each y-slice pools rows i = ys, ys+YS, ys+2*YS, ...
    // Manual 4x unroll -> up to 4 independent loads in flight per thread.
    int i = ys;
    for (; i + 3 * YS < cnt; i += 4 * YS) {
        float4 v0 = __ldg(src + (size_t)(i + 0 * YS) * D4);
        float4 v1 = __ldg(src + (size_t)(i + 1 * YS) * D4);
        float4 v2 = __ldg(src + (size_t)(i + 2 * YS) * D4);
        float4 v3 = __ldg(src + (size_t)(i + 3 * YS) * D4);
        acc = f4max(acc, f4max(f4max(v0, v1), f4max(v2, v3)));
    }
    for (; i < cnt; i += YS) {
        acc = f4max(acc, __ldg(src + (size_t)i * D4));
    }

    red[ys][lane] = acc;
    __syncthreads();

    if (ys == 0) {
        float4 r = f4max(f4max(red[0][lane], red[1][lane]),
                         f4max(red[2][lane], red[3][lane]));
        ((float4*)(out + out_off))[lane] = r;
    }
}

extern "C" void kernel_launch(void* const* d_in, const int* in_sizes, int n_in,
                              void* d_out, int out_size) {
    // metadata order: topic_reps, word_reps, topic_lens(int64, unused),
    //                 para_spans, x_spans, shell_spans
    const float* topic_reps  = (const float*)d_in[0];
    const float* word_reps   = (const float*)d_in[1];
    const int*   para_spans  = (const int*)d_in[3];
    const int*   x_spans     = (const int*)d_in[4];
    const int*   shell_spans = (const int*)d_in[5];
    float* out = (float*)d_out;

    dim3 block(64, YS);        // 256 threads
    dim3 grid(ROWS_TOTAL);     // 456 blocks, one per output row
    span_maxpool_kernel<<<grid, block>>>(topic_reps, word_reps,
                                         para_spans, x_spans, shell_spans, out);
}